// round 11
// baseline (speedup 1.0000x reference)
#include <cuda_runtime.h>

#define NCTA 128
#define NTHR 512
#define SW   2052                      // W row stride (floats)
#define SAWN 12                        // A row stride (floats), 8k + pad
#define ABUFN (32 * SAWN)              // 384 floats: one [32m x 8k] buffer
#define A_OFF (16 * SW)                // 32832
#define BIAS_OFF (A_OFF + 16 * 3 * ABUFN)   // 51264
#define SMEM_FLOATS (BIAS_OFF + 16)    // 205120 B
#define HNOFF (512 * 64 * 1024)

__device__ float g_h1[3][64 * 1024];   // layer-0 h, mod-3 (read distance 2)
__device__ float g_h2[2][64 * 1024];   // layer-1 h, mod-2
__device__ unsigned g_cnt, g_gen;

__device__ __forceinline__ unsigned su32(const void* p) {
    return (unsigned)__cvta_generic_to_shared(p);
}
#define CP16(d, s) asm volatile("cp.async.cg.shared.global [%0],[%1],16;" :: "r"(d), "l"(s))
#define CPCOMMIT() asm volatile("cp.async.commit_group;")
#define FMA2(c, a, b) asm("fma.rn.f32x2 %0,%1,%2,%0;" : "+l"(c) : "l"(a), "l"(b))
#define LDS2U64(lo, hi, ad) \
    asm volatile("ld.shared.v2.u64 {%0,%1},[%2];" : "=l"(lo), "=l"(hi) : "r"(ad))

union UF { unsigned long long u; float2 f; };

__device__ __forceinline__ unsigned ld_vol(const unsigned* p) {
    unsigned v;
    asm volatile("ld.volatile.global.u32 %0,[%1];" : "=r"(v) : "l"(p));
    return v;
}
__device__ __forceinline__ void st_vol(unsigned* p, unsigned v) {
    asm volatile("st.volatile.global.u32 [%0],%1;" :: "l"(p), "r"(v));
}

__device__ __forceinline__ float fast_tanh(float v) {
    float e = __expf(2.0f * v);
    return 1.0f - __fdividef(2.0f, e + 1.0f);
}

__global__ void rnn_init(const float* __restrict__ h0) {
    int i = blockIdx.x * blockDim.x + threadIdx.x;
    const int n = 64 * 1024;
    for (int idx = i; idx < n; idx += gridDim.x * blockDim.x) {
        g_h1[2][idx] = h0[idx];        // h1[t=-1] in slot 2
        g_h2[1][idx] = h0[n + idx];    // h2[t=-1] in slot 1
    }
    if (i == 0) { g_cnt = 0u; g_gen = 0u; }
}

__global__ void __launch_bounds__(NTHR, 1) rnn_main(
    const float* __restrict__ x,
    const float* __restrict__ Wx, const float* __restrict__ bx,
    const float* __restrict__ Wh, const float* __restrict__ bh,
    float* __restrict__ out, int out_size)
{
    extern __shared__ float sm[];
    const int tid = threadIdx.x, cta = blockIdx.x;
    const int layer = cta >> 6, col0 = (cta & 63) * 16;

    // ---- load fused [16 j][2048 k] weight slice into SMEM once ----
    {
        const float* wxl = Wx + (size_t)layer * 1024 * 1024;
        const float* whl = Wh + (size_t)layer * 1024 * 1024;
        unsigned wb = su32(sm);
#pragma unroll 4
        for (int r = 0; r < 16; r++) {
            int idx = r * NTHR + tid;
            int j = idx >> 9;
            int k4 = (idx & 511) * 4;
            const float* src = (k4 < 1024)
                ? wxl + (size_t)(col0 + j) * 1024 + k4
                : whl + (size_t)(col0 + j) * 1024 + (k4 - 1024);
            CP16(wb + (unsigned)(j * SW + k4) * 4u, src);
        }
        CPCOMMIT();
        if (tid < 16)
            sm[BIAS_OFF + tid] = bx[layer * 1024 + col0 + tid]
                               + bh[layer * 1024 + col0 + tid];
        asm volatile("cp.async.wait_group 0;");
        __syncthreads();
    }

    // 16 warps = 2 m-halves x 8 k-ranges (128 k each half-matrix)
    // lanes = mg(4) x jq(4) x ks(2); lane tile 8m x 4j, 4k per sub
    const int wid = tid >> 5, lane = tid & 31;
    const int half = wid & 1, kr = wid >> 1;
    const int mg = lane & 3, jq = (lane >> 2) & 3, ks = lane >> 4;
    const bool wr_hn = out_size >= HNOFF + 2 * 64 * 1024;
    const unsigned awarp = su32(sm) + (unsigned)(A_OFF + wid * 3 * ABUFN) * 4u;
    const unsigned wjq = su32(sm) + (unsigned)(jq * SW) * 4u;
    float* red = sm + A_OFF;

    unsigned long long acc[8][4];

    // stage one [32 m][8 k] sub-chunk of this warp's k-range into buffer b
    auto stage = [&](const float* s0, int sub, int b) {
        unsigned d0 = awarp + (unsigned)(b * ABUFN) * 4u;
        const float* sp = s0 + sub * 8;
#pragma unroll
        for (int r = 0; r < 2; r++) {
            int idx = r * 32 + lane;
            int mrow = idx >> 1, q = idx & 1;
            CP16(d0 + (unsigned)(mrow * SAWN + q * 4) * 4u,
                 sp + (size_t)(half * 32 + mrow) * 1024 + q * 4);
        }
        CPCOMMIT();
    };

    // one half-GEMM: srcm row-major [64][1024]; W columns start at hb
    auto ghalf = [&](const float* srcm, int hb) {
        const float* s0 = srcm + kr * 128;
        stage(s0, 0, 0);
        stage(s0, 1, 1);
        const unsigned wjk = wjq + (unsigned)(hb + kr * 128 + ks * 4) * 4u;
        for (int sub = 0; sub < 16; sub++) {
            if (sub < 14) {
                stage(s0, sub + 2, (sub + 2) % 3);
                asm volatile("cp.async.wait_group 2;");
            } else if (sub == 14) {
                asm volatile("cp.async.wait_group 1;");
            } else {
                asm volatile("cp.async.wait_group 0;");
            }
            __syncwarp();
            const unsigned ab = awarp
                + (unsigned)((sub % 3) * ABUFN + mg * SAWN + ks * 4) * 4u;
            const unsigned wk = wjk + (unsigned)(sub * 8) * 4u;
            unsigned long long w0[4], w1[4];
#pragma unroll
            for (int jj = 0; jj < 4; jj++)
                LDS2U64(w0[jj], w1[jj], wk + jj * (4 * SW * 4));
#pragma unroll
            for (int i = 0; i < 8; i++) {
                unsigned long long a0, a1;
                LDS2U64(a0, a1, ab + i * (4 * SAWN * 4));
#pragma unroll
                for (int jj = 0; jj < 4; jj++) {
                    FMA2(acc[i][jj], a0, w0[jj]);
                    FMA2(acc[i][jj], a1, w1[jj]);
                }
            }
            __syncwarp();
        }
    };

    for (int p = 0; p <= 513; p++) {
        const bool act = (layer == 0) ? (p < 512) : (p >= 2);
        if (act) {
            const int t = (layer == 0) ? p : p - 2;
            const float* src_inp = (layer == 0) ? x + (size_t)t * 65536
                                                : g_h1[(p - 2) % 3];
            const float* src_rec = (layer == 0) ? g_h1[(p + 2) % 3]
                                                : g_h2[(p + 1) & 1];
            float* hout = (layer == 0) ? g_h1[p % 3] : g_h2[p & 1];

#pragma unroll
            for (int i = 0; i < 8; i++)
#pragma unroll
                for (int jj = 0; jj < 4; jj++) acc[i][jj] = 0ull;

            ghalf(src_inp, 0);                         // pre-flip work

            while (ld_vol(&g_gen) < (unsigned)p) {}    // per-warp spin
            __syncwarp();

            ghalf(src_rec, 1024);                      // post-flip work

            // ---- reduction: ks-pair shfl, then red[kr][64 m][16 j] ----
            __syncthreads();
#pragma unroll
            for (int i = 0; i < 8; i++)
#pragma unroll
                for (int jj = 0; jj < 4; jj++) {
                    UF u; u.u = acc[i][jj];
                    float r = u.f.x + u.f.y;
                    r += __shfl_xor_sync(0xffffffffu, r, 16);
                    if (lane < 16)
                        red[kr * 1024 + (half * 32 + mg + 4 * i) * 16
                            + (jq + 4 * jj)] = r;
                }
            __syncthreads();
            {
                const int m = tid >> 3, jc = (tid & 7) * 2;
                float2 s2 = make_float2(0.f, 0.f);
#pragma unroll
                for (int k8 = 0; k8 < 8; k8++) {
                    float2 v = *(const float2*)&red[k8 * 1024 + m * 16 + jc];
                    s2.x += v.x; s2.y += v.y;
                }
                float2 b2 = *(const float2*)&sm[BIAS_OFF + jc];
                float2 h2;
                h2.x = fast_tanh(s2.x + b2.x);
                h2.y = fast_tanh(s2.y + b2.y);
                *(float2*)&hout[m * 1024 + col0 + jc] = h2;
                if (layer == 1) {
                    float2 o2 = make_float2(10.f * h2.x, 10.f * h2.y);
                    *(float2*)&out[(size_t)t * 65536 + m * 1024 + col0 + jc] = o2;
                }
                if (wr_hn && t == 511)
                    *(float2*)&out[HNOFF + (size_t)layer * 65536
                                   + m * 1024 + col0 + jc] = h2;
            }
        } else {
            while (ld_vol(&g_gen) < (unsigned)p) {}
        }
        __syncthreads();
        if (tid == 0) {
            __threadfence();
            if (atomicAdd(&g_cnt, 1u) == NCTA - 1u) {
                st_vol(&g_cnt, 0u);
                __threadfence();
                st_vol(&g_gen, (unsigned)p + 1u);
            }
        }
    }
}

extern "C" void kernel_launch(void* const* d_in, const int* in_sizes, int n_in,
                              void* d_out, int out_size) {
    const float* x  = (const float*)d_in[0];
    const float* h0 = (const float*)d_in[1];
    const float* Wx = (const float*)d_in[2];
    const float* bx = (const float*)d_in[3];
    const float* Wh = (const float*)d_in[4];
    const float* bh = (const float*)d_in[5];
    (void)in_sizes; (void)n_in;

    cudaFuncSetAttribute(rnn_main, cudaFuncAttributeMaxDynamicSharedMemorySize,
                         SMEM_FLOATS * 4);
    rnn_init<<<64, 256>>>(h0);
    rnn_main<<<NCTA, NTHR, SMEM_FLOATS * 4>>>(x, Wx, bx, Wh, bh,
                                              (float*)d_out, out_size);
}

// round 12
// speedup vs baseline: 1.0989x; 1.0989x over previous
#include <cuda_runtime.h>

#define NCTA 128
#define NTHR 512
#define SW   2056                      // W row stride (floats), ==8 mod 32
#define A_OFF (16 * SW)                // 32896 floats
#define BIAS_OFF (A_OFF + 16 * 1024)   // 49280 (16 warps x 4 bufs x 256 floats)
#define SMEM_FLOATS (BIAS_OFF + 16)    // 197184 B
#define HNOFF (512 * 64 * 1024)

__device__ float g_h1[3][64 * 1024];   // layer-0 h, mod-3 (read distance 2)
__device__ float g_h2[2][64 * 1024];   // layer-1 h, mod-2
__device__ unsigned g_cnt, g_gen;

__device__ __forceinline__ unsigned su32(const void* p) {
    return (unsigned)__cvta_generic_to_shared(p);
}
#define CP16(d, s) asm volatile("cp.async.cg.shared.global [%0],[%1],16;" :: "r"(d), "l"(s))
#define CPCOMMIT() asm volatile("cp.async.commit_group;")
#define FMA2(c, a, b) asm("fma.rn.f32x2 %0,%1,%2,%0;" : "+l"(c) : "l"(a), "l"(b))
#define LDS2U64(lo, hi, ad) \
    asm volatile("ld.shared.v2.u64 {%0,%1},[%2];" : "=l"(lo), "=l"(hi) : "r"(ad))

union UF { unsigned long long u; float2 f; };

__device__ __forceinline__ unsigned ld_vol(const unsigned* p) {
    unsigned v;
    asm volatile("ld.volatile.global.u32 %0,[%1];" : "=r"(v) : "l"(p));
    return v;
}
__device__ __forceinline__ void st_vol(unsigned* p, unsigned v) {
    asm volatile("st.volatile.global.u32 [%0],%1;" :: "l"(p), "r"(v));
}

__device__ __forceinline__ float fast_tanh(float v) {
    float e = __expf(2.0f * v);
    return 1.0f - __fdividef(2.0f, e + 1.0f);
}

__global__ void rnn_init(const float* __restrict__ h0) {
    int i = blockIdx.x * blockDim.x + threadIdx.x;
    const int n = 64 * 1024;
    for (int idx = i; idx < n; idx += gridDim.x * blockDim.x) {
        g_h1[2][idx] = h0[idx];        // h1[t=-1] in slot 2
        g_h2[1][idx] = h0[n + idx];    // h2[t=-1] in slot 1
    }
    if (i == 0) { g_cnt = 0u; g_gen = 0u; }
}

__global__ void __launch_bounds__(NTHR, 1) rnn_main(
    const float* __restrict__ x,
    const float* __restrict__ Wx, const float* __restrict__ bx,
    const float* __restrict__ Wh, const float* __restrict__ bh,
    float* __restrict__ out, int out_size)
{
    extern __shared__ float sm[];
    const int tid = threadIdx.x, cta = blockIdx.x;
    const int layer = cta >> 6, col0 = (cta & 63) * 16;

    // ---- load fused [16 j][2048 k] weight slice into SMEM once ----
    {
        const float* wxl = Wx + (size_t)layer * 1024 * 1024;
        const float* whl = Wh + (size_t)layer * 1024 * 1024;
        unsigned wb = su32(sm);
#pragma unroll 4
        for (int r = 0; r < 16; r++) {
            int idx = r * NTHR + tid;
            int j = idx >> 9;
            int k4 = (idx & 511) * 4;
            const float* src = (k4 < 1024)
                ? wxl + (size_t)(col0 + j) * 1024 + k4
                : whl + (size_t)(col0 + j) * 1024 + (k4 - 1024);
            CP16(wb + (unsigned)(j * SW + k4) * 4u, src);
        }
        CPCOMMIT();
        if (tid < 16)
            sm[BIAS_OFF + tid] = bx[layer * 1024 + col0 + tid]
                               + bh[layer * 1024 + col0 + tid];
        asm volatile("cp.async.wait_group 0;");
        __syncthreads();
    }

    // 16 warps = 2 m-halves x 8 k-ranges (128 k per half-matrix each)
    // lanes: mg(4) x jq(4) x ks(2); lane tile 8m x 4j, 4k per sub
    const int wid = tid >> 5, lane = tid & 31;
    const int half = wid & 1, kr = wid >> 1;
    const int mg = lane & 3, jq = (lane >> 2) & 3, ks = lane >> 4;
    const bool wr_hn = out_size >= HNOFF + 2 * 64 * 1024;
    // per-warp A region: 4 ring buffers x 1024 B ([32 m][8 k] each)
    const unsigned awarp = su32(sm) + (unsigned)A_OFF * 4u + (unsigned)(wid * 4096);
    const unsigned wjq = su32(sm) + (unsigned)(jq * SW) * 4u;
    float* red = sm + A_OFF;

    unsigned long long acc[8][4];

    // stage [32 m][8 k] sub-chunk into ring buffer b (2 CP16/lane)
    auto stage = [&](const float* s0, int sub, int b) {
        const float* sp = s0 + sub * 8;
        unsigned d0 = awarp + (unsigned)(b * 1024);
#pragma unroll
        for (int r = 0; r < 2; r++) {
            int idx = r * 32 + lane;
            int m = idx >> 1, q = idx & 1;
            CP16(d0 + (unsigned)(m * 32 + q * 16),
                 sp + (size_t)(half * 32 + m) * 1024 + q * 4);
        }
        CPCOMMIT();
    };

    // one half-GEMM: srcm row-major [64][1024]; W columns start at hb
    auto ghalf = [&](const float* srcm, int hb) {
        const float* s0 = srcm + kr * 128;
        stage(s0, 0, 0); stage(s0, 1, 1); stage(s0, 2, 2);
        unsigned wk = wjq + (unsigned)((hb + kr * 128 + ks * 4) * 4);
        for (int sub = 0; sub < 16; sub++) {
            if (sub < 13) {
                stage(s0, sub + 3, (sub + 3) & 3);
                asm volatile("cp.async.wait_group 3;");
            } else if (sub == 13) {
                asm volatile("cp.async.wait_group 2;");
            } else if (sub == 14) {
                asm volatile("cp.async.wait_group 1;");
            } else {
                asm volatile("cp.async.wait_group 0;");
            }
            __syncwarp();
            const unsigned ab = awarp
                + (unsigned)((sub & 3) * 1024 + mg * 32 + ks * 16);
            unsigned long long w0[4], w1[4];
#pragma unroll
            for (int jj = 0; jj < 4; jj++)
                LDS2U64(w0[jj], w1[jj], wk + jj * (4 * SW * 4));
#pragma unroll
            for (int i = 0; i < 8; i++) {
                unsigned long long a0, a1;
                LDS2U64(a0, a1, ab + i * 128);
#pragma unroll
                for (int jj = 0; jj < 4; jj++) {
                    FMA2(acc[i][jj], a0, w0[jj]);
                    FMA2(acc[i][jj], a1, w1[jj]);
                }
            }
            wk += 32;                                  // advance 8 k
            __syncwarp();
        }
    };

    for (int p = 0; p <= 513; p++) {
        const bool act = (layer == 0) ? (p < 512) : (p >= 2);
        if (act) {
            const int t = (layer == 0) ? p : p - 2;
            const float* src_inp = (layer == 0) ? x + (size_t)t * 65536
                                                : g_h1[(p - 2) % 3];
            const float* src_rec = (layer == 0) ? g_h1[(p + 2) % 3]
                                                : g_h2[(p + 1) & 1];
            float* hout = (layer == 0) ? g_h1[p % 3] : g_h2[p & 1];

#pragma unroll
            for (int i = 0; i < 8; i++)
#pragma unroll
                for (int jj = 0; jj < 4; jj++) acc[i][jj] = 0ull;

            ghalf(src_inp, 0);                         // pre-flip work

            while (ld_vol(&g_gen) < (unsigned)p) {}    // per-warp spin
            __syncwarp();

            ghalf(src_rec, 1024);                      // post-flip work

            // ---- reduction: ks-pair shfl, then red[kr][64 m][16 j] ----
            __syncthreads();
#pragma unroll
            for (int i = 0; i < 8; i++)
#pragma unroll
                for (int jj = 0; jj < 4; jj++) {
                    UF u; u.u = acc[i][jj];
                    float r = u.f.x + u.f.y;
                    r += __shfl_xor_sync(0xffffffffu, r, 16);
                    if (lane < 16)
                        red[kr * 1024 + (half * 32 + mg + 4 * i) * 16
                            + (jq + 4 * jj)] = r;
                }
            __syncthreads();
            {
                const int m = tid >> 3, jc = (tid & 7) * 2;
                float2 s2 = make_float2(0.f, 0.f);
#pragma unroll
                for (int k8 = 0; k8 < 8; k8++) {
                    float2 v = *(const float2*)&red[k8 * 1024 + m * 16 + jc];
                    s2.x += v.x; s2.y += v.y;
                }
                float2 b2 = *(const float2*)&sm[BIAS_OFF + jc];
                float2 h2;
                h2.x = fast_tanh(s2.x + b2.x);
                h2.y = fast_tanh(s2.y + b2.y);
                *(float2*)&hout[m * 1024 + col0 + jc] = h2;
                if (layer == 1) {
                    float2 o2 = make_float2(10.f * h2.x, 10.f * h2.y);
                    *(float2*)&out[(size_t)t * 65536 + m * 1024 + col0 + jc] = o2;
                }
                if (wr_hn && t == 511)
                    *(float2*)&out[HNOFF + (size_t)layer * 65536
                                   + m * 1024 + col0 + jc] = h2;
            }
        } else {
            while (ld_vol(&g_gen) < (unsigned)p) {}
        }
        __syncthreads();
        if (tid == 0) {
            __threadfence();
            if (atomicAdd(&g_cnt, 1u) == NCTA - 1u) {
                st_vol(&g_cnt, 0u);
                __threadfence();
                st_vol(&g_gen, (unsigned)p + 1u);
            }
        }
    }
}

extern "C" void kernel_launch(void* const* d_in, const int* in_sizes, int n_in,
                              void* d_out, int out_size) {
    const float* x  = (const float*)d_in[0];
    const float* h0 = (const float*)d_in[1];
    const float* Wx = (const float*)d_in[2];
    const float* bx = (const float*)d_in[3];
    const float* Wh = (const float*)d_in[4];
    const float* bh = (const float*)d_in[5];
    (void)in_sizes; (void)n_in;

    cudaFuncSetAttribute(rnn_main, cudaFuncAttributeMaxDynamicSharedMemorySize,
                         SMEM_FLOATS * 4);
    rnn_init<<<64, 256>>>(h0);
    rnn_main<<<NCTA, NTHR, SMEM_FLOATS * 4>>>(x, Wx, bx, Wh, bh,
                                              (float*)d_out, out_size);
}

// round 13
// speedup vs baseline: 1.1003x; 1.0013x over previous
#include <cuda_runtime.h>

#define NCTA 128
#define NTHR 512
#define SW   2056                      // W row stride (floats), ==8 mod 32
#define A_OFF (16 * SW)                // 32896 floats
#define BIAS_OFF (A_OFF + 16 * 1024)   // 49280 (16 warps x 4 bufs x 256 floats)
#define SMEM_FLOATS (BIAS_OFF + 16)    // 197184 B
#define HNOFF (512 * 64 * 1024)

__device__ float g_h1[3][64 * 1024];   // layer-0 h, mod-3 (read distance 2)
__device__ float g_h2[2][64 * 1024];   // layer-1 h, mod-2
__device__ unsigned g_cnt, g_gen;

__device__ __forceinline__ unsigned su32(const void* p) {
    return (unsigned)__cvta_generic_to_shared(p);
}
#define CP16(d, s) asm volatile("cp.async.cg.shared.global [%0],[%1],16;" :: "r"(d), "l"(s))
#define CPCOMMIT() asm volatile("cp.async.commit_group;")
#define FMA2(c, a, b) asm("fma.rn.f32x2 %0,%1,%2,%0;" : "+l"(c) : "l"(a), "l"(b))
#define LDS2U64(lo, hi, ad) \
    asm volatile("ld.shared.v2.u64 {%0,%1},[%2];" : "=l"(lo), "=l"(hi) : "r"(ad))

union UF { unsigned long long u; float2 f; };

__device__ __forceinline__ unsigned ld_vol(const unsigned* p) {
    unsigned v;
    asm volatile("ld.volatile.global.u32 %0,[%1];" : "=r"(v) : "l"(p));
    return v;
}
__device__ __forceinline__ void st_vol(unsigned* p, unsigned v) {
    asm volatile("st.volatile.global.u32 [%0],%1;" :: "l"(p), "r"(v));
}

__device__ __forceinline__ float fast_tanh(float v) {
    float e = __expf(2.0f * v);
    return 1.0f - __fdividef(2.0f, e + 1.0f);
}

__global__ void rnn_init(const float* __restrict__ h0) {
    int i = blockIdx.x * blockDim.x + threadIdx.x;
    const int n = 64 * 1024;
    for (int idx = i; idx < n; idx += gridDim.x * blockDim.x) {
        g_h1[2][idx] = h0[idx];        // h1[t=-1] in slot 2
        g_h2[1][idx] = h0[n + idx];    // h2[t=-1] in slot 1
    }
    if (i == 0) { g_cnt = 0u; g_gen = 0u; }
}

__global__ void __launch_bounds__(NTHR, 1) rnn_main(
    const float* __restrict__ x,
    const float* __restrict__ Wx, const float* __restrict__ bx,
    const float* __restrict__ Wh, const float* __restrict__ bh,
    float* __restrict__ out, int out_size)
{
    extern __shared__ float sm[];
    const int tid = threadIdx.x, cta = blockIdx.x;
    const int layer = cta >> 6, col0 = (cta & 63) * 16;

    // ---- load fused [16 j][2048 k] weight slice into SMEM once ----
    {
        const float* wxl = Wx + (size_t)layer * 1024 * 1024;
        const float* whl = Wh + (size_t)layer * 1024 * 1024;
        unsigned wb = su32(sm);
#pragma unroll 4
        for (int r = 0; r < 16; r++) {
            int idx = r * NTHR + tid;
            int j = idx >> 9;
            int k4 = (idx & 511) * 4;
            const float* src = (k4 < 1024)
                ? wxl + (size_t)(col0 + j) * 1024 + k4
                : whl + (size_t)(col0 + j) * 1024 + (k4 - 1024);
            CP16(wb + (unsigned)(j * SW + k4) * 4u, src);
        }
        CPCOMMIT();
        if (tid < 16)
            sm[BIAS_OFF + tid] = bx[layer * 1024 + col0 + tid]
                               + bh[layer * 1024 + col0 + tid];
        asm volatile("cp.async.wait_group 0;");
        __syncthreads();
    }

    // 16 warps = 2 m-halves x 8 k-ranges (128 k per half-matrix each)
    // lanes: mg(4) x jq(4) x ks(2); lane tile 8m x 4j, 4k per sub
    const int wid = tid >> 5, lane = tid & 31;
    const int half = wid & 1, kr = wid >> 1;
    const int mg = lane & 3, jq = (lane >> 2) & 3, ks = lane >> 4;
    const bool wr_hn = out_size >= HNOFF + 2 * 64 * 1024;
    // per-warp A region: 4 ring buffers x 1024 B ([32 m][8 k] each)
    const unsigned awarp = su32(sm) + (unsigned)A_OFF * 4u + (unsigned)(wid * 4096);
    const unsigned wjq = su32(sm) + (unsigned)(jq * SW) * 4u;
    float* red = sm + A_OFF;

    unsigned long long acc[8][4];

    // stage [32 m][8 k] sub-chunk into ring buffer b (2 CP16/lane)
    auto stage = [&](const float* s0, int sub, int b) {
        const float* sp = s0 + sub * 8;
        unsigned d0 = awarp + (unsigned)(b * 1024);
#pragma unroll
        for (int r = 0; r < 2; r++) {
            int idx = r * 32 + lane;
            int m = idx >> 1, q = idx & 1;
            CP16(d0 + (unsigned)(m * 32 + q * 16),
                 sp + (size_t)(half * 32 + m) * 1024 + q * 4);
        }
        CPCOMMIT();
    };

    // one half-GEMM: srcm row-major [64][1024]; W columns start at hb
    auto ghalf = [&](const float* srcm, int hb) {
        const float* s0 = srcm + kr * 128;
        stage(s0, 0, 0); stage(s0, 1, 1); stage(s0, 2, 2);
        unsigned wk = wjq + (unsigned)((hb + kr * 128 + ks * 4) * 4);
        for (int sub = 0; sub < 16; sub++) {
            if (sub < 13) {
                stage(s0, sub + 3, (sub + 3) & 3);
                asm volatile("cp.async.wait_group 3;");
            } else if (sub == 13) {
                asm volatile("cp.async.wait_group 2;");
            } else if (sub == 14) {
                asm volatile("cp.async.wait_group 1;");
            } else {
                asm volatile("cp.async.wait_group 0;");
            }
            __syncwarp();
            const unsigned ab = awarp
                + (unsigned)((sub & 3) * 1024 + mg * 32 + ks * 16);
            unsigned long long w0[4], w1[4];
#pragma unroll
            for (int jj = 0; jj < 4; jj++)
                LDS2U64(w0[jj], w1[jj], wk + jj * (4 * SW * 4));
#pragma unroll
            for (int i = 0; i < 8; i++) {
                unsigned long long a0, a1;
                LDS2U64(a0, a1, ab + i * 128);
#pragma unroll
                for (int jj = 0; jj < 4; jj++) {
                    FMA2(acc[i][jj], a0, w0[jj]);
                    FMA2(acc[i][jj], a1, w1[jj]);
                }
            }
            wk += 32;                                  // advance 8 k
            __syncwarp();
        }
    };

    for (int p = 0; p <= 513; p++) {
        const bool act = (layer == 0) ? (p < 512) : (p >= 2);
        if (act) {
            const int t = (layer == 0) ? p : p - 2;
            const float* src_inp = (layer == 0) ? x + (size_t)t * 65536
                                                : g_h1[(p - 2) % 3];
            const float* src_rec = (layer == 0) ? g_h1[(p + 2) % 3]
                                                : g_h2[(p + 1) & 1];
            float* hout = (layer == 0) ? g_h1[p % 3] : g_h2[p & 1];

#pragma unroll
            for (int i = 0; i < 8; i++)
#pragma unroll
                for (int jj = 0; jj < 4; jj++) acc[i][jj] = 0ull;

            ghalf(src_inp, 0);                         // pre-flip work

            while (ld_vol(&g_gen) < (unsigned)p) {}    // per-warp spin
            __syncwarp();

            ghalf(src_rec, 1024);                      // post-flip work

            // ---- reduction: ks-pair shfl, then red[kr][64 m][16 j] ----
            __syncthreads();
#pragma unroll
            for (int i = 0; i < 8; i++)
#pragma unroll
                for (int jj = 0; jj < 4; jj++) {
                    UF u; u.u = acc[i][jj];
                    float r = u.f.x + u.f.y;
                    r += __shfl_xor_sync(0xffffffffu, r, 16);
                    if (lane < 16)
                        red[kr * 1024 + (half * 32 + mg + 4 * i) * 16
                            + (jq + 4 * jj)] = r;
                }
            __syncthreads();
            {
                const int m = tid >> 3, jc = (tid & 7) * 2;
                float2 s2 = make_float2(0.f, 0.f);
#pragma unroll
                for (int k8 = 0; k8 < 8; k8++) {
                    float2 v = *(const float2*)&red[k8 * 1024 + m * 16 + jc];
                    s2.x += v.x; s2.y += v.y;
                }
                float2 b2 = *(const float2*)&sm[BIAS_OFF + jc];
                float2 h2;
                h2.x = fast_tanh(s2.x + b2.x);
                h2.y = fast_tanh(s2.y + b2.y);
                *(float2*)&hout[m * 1024 + col0 + jc] = h2;
                if (layer == 1) {
                    float2 o2 = make_float2(10.f * h2.x, 10.f * h2.y);
                    *(float2*)&out[(size_t)t * 65536 + m * 1024 + col0 + jc] = o2;
                }
                if (wr_hn && t == 511)
                    *(float2*)&out[HNOFF + (size_t)layer * 65536
                                   + m * 1024 + col0 + jc] = h2;
            }
        } else {
            while (ld_vol(&g_gen) < (unsigned)p) {}
        }
        __syncthreads();
        if (tid == 0) {
            __threadfence();
            if (atomicAdd(&g_cnt, 1u) == NCTA - 1u) {
                st_vol(&g_cnt, 0u);
                __threadfence();
                st_vol(&g_gen, (unsigned)p + 1u);
            }
        }
    }
}

extern "C" void kernel_launch(void* const* d_in, const int* in_sizes, int n_in,
                              void* d_out, int out_size) {
    const float* x  = (const float*)d_in[0];
    const float* h0 = (const float*)d_in[1];
    const float* Wx = (const float*)d_in[2];
    const float* bx = (const float*)d_in[3];
    const float* Wh = (const float*)d_in[4];
    const float* bh = (const float*)d_in[5];
    (void)in_sizes; (void)n_in;

    cudaFuncSetAttribute(rnn_main, cudaFuncAttributeMaxDynamicSharedMemorySize,
                         SMEM_FLOATS * 4);
    rnn_init<<<64, 256>>>(h0);
    rnn_main<<<NCTA, NTHR, SMEM_FLOATS * 4>>>(x, Wx, bx, Wh, bh,
                                              (float*)d_out, out_size);
}

// round 14
// speedup vs baseline: 1.3404x; 1.2182x over previous
#include <cuda_runtime.h>

#define NCTA 128
#define NTHR 512
#define KS   2056u                   // W bf16 row stride (elements)
#define WHI  0u
#define WLO  65792u                  // 16*2056*2
#define REDB 131584u                 // 4 kg * 64 m * 16 j * f32 = 16 KB
#define BIASB 147968u
#define SMEM_BYTES 148032
#define HNOFF (512 * 64 * 1024)

__device__ float g_h1[3][65536];     // layer-0 h, mod-3 (read distance 2)
__device__ float g_h2[2][65536];     // layer-1 h, mod-2
__device__ unsigned g_cnt, g_gen;

static __device__ __forceinline__ unsigned su32(const void* p) {
    return (unsigned)__cvta_generic_to_shared(p);
}
static __device__ __forceinline__ unsigned ld_vol(const unsigned* p) {
    unsigned v;
    asm volatile("ld.volatile.global.u32 %0,[%1];" : "=r"(v) : "l"(p));
    return v;
}
static __device__ __forceinline__ void st_vol(unsigned* p, unsigned v) {
    asm volatile("st.volatile.global.u32 [%0],%1;" :: "l"(p), "r"(v));
}
static __device__ __forceinline__ float2 ldcg2(const float* p) {
    float2 v;
    asm volatile("ld.global.cg.v2.f32 {%0,%1},[%2];"
                 : "=f"(v.x), "=f"(v.y) : "l"(p));
    return v;
}
static __device__ __forceinline__ unsigned lds32(unsigned a) {
    unsigned v;
    asm volatile("ld.shared.u32 %0,[%1];" : "=r"(v) : "r"(a));
    return v;
}
// split one fp32 pair into bf16x2 hi (truncate) and lo (residual, rn)
static __device__ __forceinline__ void split2(float2 v, unsigned& h, unsigned& l) {
    unsigned u0 = __float_as_uint(v.x), u1 = __float_as_uint(v.y);
    asm("prmt.b32 %0,%1,%2,0x7632;" : "=r"(h) : "r"(u0), "r"(u1));
    float l0 = v.x - __uint_as_float(u0 & 0xFFFF0000u);
    float l1 = v.y - __uint_as_float(u1 & 0xFFFF0000u);
    asm("cvt.rn.bf16x2.f32 %0,%1,%2;" : "=r"(l) : "f"(l1), "f"(l0));
}
#define MMA(c, A0, A1, A2, A3, B0, B1) \
    asm("mma.sync.aligned.m16n8k16.row.col.f32.bf16.bf16.f32 " \
        "{%0,%1,%2,%3},{%4,%5,%6,%7},{%8,%9},{%0,%1,%2,%3};" \
        : "+f"(c[0]), "+f"(c[1]), "+f"(c[2]), "+f"(c[3]) \
        : "r"(A0), "r"(A1), "r"(A2), "r"(A3), "r"(B0), "r"(B1))

static __device__ __forceinline__ float fast_tanh(float v) {
    float e = __expf(2.0f * v);
    return 1.0f - __fdividef(2.0f, e + 1.0f);
}

__global__ void rnn_init(const float* __restrict__ h0) {
    int i = blockIdx.x * blockDim.x + threadIdx.x;
    const int n = 65536;
    for (int idx = i; idx < n; idx += gridDim.x * blockDim.x) {
        g_h1[2][idx] = h0[idx];
        g_h2[1][idx] = h0[n + idx];
    }
    if (i == 0) { g_cnt = 0u; g_gen = 0u; }
}

__global__ void __launch_bounds__(NTHR, 1) rnn_main(
    const float* __restrict__ x,
    const float* __restrict__ Wx, const float* __restrict__ bx,
    const float* __restrict__ Wh, const float* __restrict__ bh,
    float* __restrict__ out, int out_size)
{
    extern __shared__ char smem[];
    float* red = (float*)(smem + REDB);
    float* bias = (float*)(smem + BIASB);
    const int tid = threadIdx.x, cta = blockIdx.x;
    const int layer = cta >> 6, col0 = (cta & 63) * 16;

    // ---- convert fused W slice [16 j][2048 k] fp32 -> bf16 hi/lo in SMEM ----
    {
        const float* wxl = Wx + (size_t)layer * 1048576 + (size_t)col0 * 1024;
        const float* whl = Wh + (size_t)layer * 1048576 + (size_t)col0 * 1024;
        for (int r = 0; r < 32; r++) {
            int idx = r * NTHR + tid;       // 16384 fp32-pairs
            int j = idx >> 10, kp = idx & 1023;
            int k = kp * 2;
            const float* s = (k < 1024) ? wxl + j * 1024 + k
                                        : whl + j * 1024 + (k - 1024);
            float2 v = *(const float2*)s;
            unsigned hp, lp;
            split2(v, hp, lp);
            *(unsigned*)(smem + WHI + ((unsigned)j * KS + k) * 2u) = hp;
            *(unsigned*)(smem + WLO + ((unsigned)j * KS + k) * 2u) = lp;
        }
        if (tid < 16)
            bias[tid] = bx[layer * 1024 + col0 + tid]
                      + bh[layer * 1024 + col0 + tid];
        __syncthreads();
    }

    // 16 warps = 4 m-tiles x 4 k-groups; lane roles per mma fragment spec
    const int wid = tid >> 5, lane = tid & 31;
    const int mt = wid & 3, kg = wid >> 2;
    const int lq = lane >> 2, lr = lane & 3;       // lq: row-in-tile / n-col
    const int r0 = mt * 16 + lq, r1 = r0 + 8;
    const bool wr_hn = out_size >= HNOFF + 131072;
    const unsigned sbase = su32(smem);
    // W byte offset for this lane (n handled by +8*KS*2; k advances per iter)
    const unsigned wlane = sbase + ((unsigned)lq * KS + (unsigned)(kg * 16 + lr * 2)) * 2u;

    float acc[2][3][4];

    // one half-GEMM over src (row-major [64][1024] fp32); W k-base = hb
    auto ghalf = [&](const float* src, unsigned hb) {
        const float* p0 = src + (size_t)r0 * 1024 + kg * 16 + lr * 2;
        const float* p1 = src + (size_t)r1 * 1024 + kg * 16 + lr * 2;
        float2 pa0 = ldcg2(p0), pa1 = ldcg2(p1);
        float2 pa2 = ldcg2(p0 + 8), pa3 = ldcg2(p1 + 8);
        unsigned wk = wlane + hb * 2u;
#pragma unroll 4
        for (int i = 0; i < 16; i++) {
            float2 c0 = pa0, c1 = pa1, c2 = pa2, c3 = pa3;
            if (i < 15) {
                p0 += 64; p1 += 64;
                pa0 = ldcg2(p0); pa1 = ldcg2(p1);
                pa2 = ldcg2(p0 + 8); pa3 = ldcg2(p1 + 8);
            }
            unsigned ah0, al0, ah1, al1, ah2, al2, ah3, al3;
            split2(c0, ah0, al0); split2(c1, ah1, al1);
            split2(c2, ah2, al2); split2(c3, ah3, al3);
#pragma unroll
            for (int n = 0; n < 2; n++) {
                unsigned wn = wk + (unsigned)n * (8u * KS * 2u);
                unsigned bh0 = lds32(wn + WHI), bh1 = lds32(wn + WHI + 16u);
                unsigned bl0 = lds32(wn + WLO), bl1 = lds32(wn + WLO + 16u);
                MMA(acc[n][0], ah0, ah1, ah2, ah3, bh0, bh1);
                MMA(acc[n][1], al0, al1, al2, al3, bh0, bh1);
                MMA(acc[n][2], ah0, ah1, ah2, ah3, bl0, bl1);
            }
            wk += 128u;                    // advance 64 k (bf16 bytes)
        }
    };

    for (int p = 0; p <= 513; p++) {
        const bool act = (layer == 0) ? (p < 512) : (p >= 2);
        if (act) {
            const int t = (layer == 0) ? p : p - 2;
            const float* src_inp = (layer == 0) ? x + (size_t)t * 65536
                                                : g_h1[(p - 2) % 3];
            const float* src_rec = (layer == 0) ? g_h1[(p + 2) % 3]
                                                : g_h2[(p + 1) & 1];
            float* hout = (layer == 0) ? g_h1[p % 3] : g_h2[p & 1];

#pragma unroll
            for (int n = 0; n < 2; n++)
#pragma unroll
                for (int q = 0; q < 3; q++)
#pragma unroll
                    for (int e = 0; e < 4; e++) acc[n][q][e] = 0.0f;

            ghalf(src_inp, 0u);                       // pre-flip work

            while (ld_vol(&g_gen) < (unsigned)p) {}   // per-warp spin
            __syncwarp();

            ghalf(src_rec, 1024u);                    // post-flip work

            // ---- stash partials: red[kg][64 m][16 j] ----
#pragma unroll
            for (int n = 0; n < 2; n++) {
                float s0 = acc[n][0][0] + acc[n][1][0] + acc[n][2][0];
                float s1 = acc[n][0][1] + acc[n][1][1] + acc[n][2][1];
                float s2 = acc[n][0][2] + acc[n][1][2] + acc[n][2][2];
                float s3 = acc[n][0][3] + acc[n][1][3] + acc[n][2][3];
                int jn = n * 8 + lr * 2;
                *(float2*)&red[kg * 1024 + r0 * 16 + jn] = make_float2(s0, s1);
                *(float2*)&red[kg * 1024 + r1 * 16 + jn] = make_float2(s2, s3);
            }
            __syncthreads();
            {
                const int m = tid >> 3, jc = (tid & 7) * 2;
                float2 s2v = make_float2(0.f, 0.f);
#pragma unroll
                for (int g = 0; g < 4; g++) {
                    float2 v = *(const float2*)&red[g * 1024 + m * 16 + jc];
                    s2v.x += v.x; s2v.y += v.y;
                }
                float2 b2 = *(const float2*)&bias[jc];
                float2 h2;
                h2.x = fast_tanh(s2v.x + b2.x);
                h2.y = fast_tanh(s2v.y + b2.y);
                *(float2*)&hout[m * 1024 + col0 + jc] = h2;
                if (layer == 1) {
                    float2 o2 = make_float2(10.f * h2.x, 10.f * h2.y);
                    *(float2*)&out[(size_t)t * 65536 + m * 1024 + col0 + jc] = o2;
                }
                if (wr_hn && t == 511)
                    *(float2*)&out[HNOFF + (size_t)layer * 65536
                                   + m * 1024 + col0 + jc] = h2;
            }
        } else {
            while (ld_vol(&g_gen) < (unsigned)p) {}
        }
        __syncthreads();
        if (tid == 0) {
            __threadfence();
            if (atomicAdd(&g_cnt, 1u) == NCTA - 1u) {
                st_vol(&g_cnt, 0u);
                __threadfence();
                st_vol(&g_gen, (unsigned)p + 1u);
            }
        }
    }
}

extern "C" void kernel_launch(void* const* d_in, const int* in_sizes, int n_in,
                              void* d_out, int out_size) {
    const float* x  = (const float*)d_in[0];
    const float* h0 = (const float*)d_in[1];
    const float* Wx = (const float*)d_in[2];
    const float* bx = (const float*)d_in[3];
    const float* Wh = (const float*)d_in[4];
    const float* bh = (const float*)d_in[5];
    (void)in_sizes; (void)n_in;

    cudaFuncSetAttribute(rnn_main, cudaFuncAttributeMaxDynamicSharedMemorySize,
                         SMEM_BYTES);
    rnn_init<<<64, 256>>>(h0);
    rnn_main<<<NCTA, NTHR, SMEM_BYTES>>>(x, Wx, bx, Wh, bh,
                                         (float*)d_out, out_size);
}

// round 15
// speedup vs baseline: 1.3903x; 1.0373x over previous
#include <cuda_runtime.h>

#define NCTA 128
#define NTHR 512
#define KS   2056u                   // W bf16 row stride (elements)
#define WHI  0u
#define WLO  65792u                  // 16*2056*2
#define REDB 131584u                 // 4 kg * 64 m * 16 j * f32
#define BIASB 147968u
#define SMEM_BYTES 148032
#define HNOFF (512 * 64 * 1024)

__device__ float g_h1[3][65536];     // layer-0 h, mod-3 (read distance 2)
__device__ float g_h2[2][65536];     // layer-1 h, mod-2
__device__ unsigned g_cnt, g_gen;

static __device__ __forceinline__ unsigned su32(const void* p) {
    return (unsigned)__cvta_generic_to_shared(p);
}
static __device__ __forceinline__ unsigned ld_vol(const unsigned* p) {
    unsigned v;
    asm volatile("ld.volatile.global.u32 %0,[%1];" : "=r"(v) : "l"(p));
    return v;
}
static __device__ __forceinline__ void st_vol(unsigned* p, unsigned v) {
    asm volatile("st.volatile.global.u32 [%0],%1;" :: "l"(p), "r"(v));
}
static __device__ __forceinline__ float2 ldcg2(const float* p) {
    float2 v;
    asm volatile("ld.global.cg.v2.f32 {%0,%1},[%2];"
                 : "=f"(v.x), "=f"(v.y) : "l"(p));
    return v;
}
// split fp32 pair -> bf16x2 hi (truncate) + lo (residual, rn)
static __device__ __forceinline__ void split2(float2 v, unsigned& h, unsigned& l) {
    unsigned u0 = __float_as_uint(v.x), u1 = __float_as_uint(v.y);
    asm("prmt.b32 %0,%1,%2,0x7632;" : "=r"(h) : "r"(u0), "r"(u1));
    float l0 = v.x - __uint_as_float(u0 & 0xFFFF0000u);
    float l1 = v.y - __uint_as_float(u1 & 0xFFFF0000u);
    asm("cvt.rn.bf16x2.f32 %0,%1,%2;" : "=r"(l) : "f"(l1), "f"(l0));
}
#define LDSMX4(r0, r1, r2, r3, a) \
    asm volatile("ldmatrix.sync.aligned.m8n8.x4.shared.b16 {%0,%1,%2,%3},[%4];" \
                 : "=r"(r0), "=r"(r1), "=r"(r2), "=r"(r3) : "r"(a))
#define MMA(c, A0, A1, A2, A3, B0, B1) \
    asm("mma.sync.aligned.m16n8k16.row.col.f32.bf16.bf16.f32 " \
        "{%0,%1,%2,%3},{%4,%5,%6,%7},{%8,%9},{%0,%1,%2,%3};" \
        : "+f"(c[0]), "+f"(c[1]), "+f"(c[2]), "+f"(c[3]) \
        : "r"(A0), "r"(A1), "r"(A2), "r"(A3), "r"(B0), "r"(B1))

static __device__ __forceinline__ float fast_tanh(float v) {
    float e = __expf(2.0f * v);
    return 1.0f - __fdividef(2.0f, e + 1.0f);
}

__global__ void rnn_init(const float* __restrict__ h0) {
    int i = blockIdx.x * blockDim.x + threadIdx.x;
    const int n = 65536;
    for (int idx = i; idx < n; idx += gridDim.x * blockDim.x) {
        g_h1[2][idx] = h0[idx];
        g_h2[1][idx] = h0[n + idx];
    }
    if (i == 0) { g_cnt = 0u; g_gen = 0u; }
}

__global__ void __launch_bounds__(NTHR, 1) rnn_main(
    const float* __restrict__ x,
    const float* __restrict__ Wx, const float* __restrict__ bx,
    const float* __restrict__ Wh, const float* __restrict__ bh,
    float* __restrict__ out, int out_size)
{
    extern __shared__ char smem[];
    float* red = (float*)(smem + REDB);
    float* bias = (float*)(smem + BIASB);
    const int tid = threadIdx.x, cta = blockIdx.x;
    const int layer = cta >> 6, col0 = (cta & 63) * 16;

    // ---- convert fused W slice [16 j][2048 k] fp32 -> bf16 hi/lo in SMEM ----
    {
        const float* wxl = Wx + (size_t)layer * 1048576 + (size_t)col0 * 1024;
        const float* whl = Wh + (size_t)layer * 1048576 + (size_t)col0 * 1024;
        for (int r = 0; r < 32; r++) {
            int idx = r * NTHR + tid;
            int j = idx >> 10, k = (idx & 1023) * 2;
            const float* s = (k < 1024) ? wxl + j * 1024 + k
                                        : whl + j * 1024 + (k - 1024);
            float2 v = *(const float2*)s;
            unsigned hp, lp;
            split2(v, hp, lp);
            *(unsigned*)(smem + WHI + ((unsigned)j * KS + k) * 2u) = hp;
            *(unsigned*)(smem + WLO + ((unsigned)j * KS + k) * 2u) = lp;
        }
        if (tid < 16)
            bias[tid] = bx[layer * 1024 + col0 + tid]
                      + bh[layer * 1024 + col0 + tid];
        __syncthreads();
    }

    // 16 warps = 4 m-tiles x 4 k-groups
    const int wid = tid >> 5, lane = tid & 31;
    const int mt = wid & 3, kg = wid >> 2;
    const int lq = lane >> 2, lr = lane & 3;
    const int r0 = mt * 16 + lq, r1 = r0 + 8;
    const bool wr_hn = out_size >= HNOFF + 131072;
    const unsigned sbase = su32(smem);
    // ldmatrix.x4 lane address: sel 0..3 -> (n-tile, k-half)
    const int sel = lane >> 3;
    const int nrow = (lane & 7) + ((sel >> 1) << 3);
    const unsigned wl0 = sbase
        + ((unsigned)nrow * KS + (unsigned)(kg * 16) + (unsigned)((sel & 1) * 8)) * 2u;

    float acc[2][3][4];

    // one half-GEMM over src (row-major [64][1024] fp32); W k-base = hb
    auto ghalf = [&](const float* src, unsigned hb) {
        const float* p0 = src + (size_t)r0 * 1024 + kg * 16 + lr * 2;
        const float* p1 = src + (size_t)r1 * 1024 + kg * 16 + lr * 2;
        float2 pa[2][4];
        pa[0][0] = ldcg2(p0);     pa[0][1] = ldcg2(p1);
        pa[0][2] = ldcg2(p0 + 8); pa[0][3] = ldcg2(p1 + 8);
        p0 += 64; p1 += 64;
        pa[1][0] = ldcg2(p0);     pa[1][1] = ldcg2(p1);
        pa[1][2] = ldcg2(p0 + 8); pa[1][3] = ldcg2(p1 + 8);
        unsigned wh = wl0 + hb * 2u;
        unsigned wl = wh + WLO;
#pragma unroll 4
        for (int i = 0; i < 16; i++) {
            float2 c0 = pa[i & 1][0], c1 = pa[i & 1][1];
            float2 c2 = pa[i & 1][2], c3 = pa[i & 1][3];
            if (i < 14) {                       // prefetch iter i+2
                p0 += 64; p1 += 64;
                pa[i & 1][0] = ldcg2(p0);     pa[i & 1][1] = ldcg2(p1);
                pa[i & 1][2] = ldcg2(p0 + 8); pa[i & 1][3] = ldcg2(p1 + 8);
            }
            unsigned bh0, bh1, bh2, bh3, bl0, bl1, bl2, bl3;
            LDSMX4(bh0, bh1, bh2, bh3, wh);
            LDSMX4(bl0, bl1, bl2, bl3, wl);
            unsigned ah0, al0, ah1, al1, ah2, al2, ah3, al3;
            split2(c0, ah0, al0); split2(c1, ah1, al1);
            split2(c2, ah2, al2); split2(c3, ah3, al3);
            MMA(acc[0][0], ah0, ah1, ah2, ah3, bh0, bh1);
            MMA(acc[0][1], al0, al1, al2, al3, bh0, bh1);
            MMA(acc[0][2], ah0, ah1, ah2, ah3, bl0, bl1);
            MMA(acc[1][0], ah0, ah1, ah2, ah3, bh2, bh3);
            MMA(acc[1][1], al0, al1, al2, al3, bh2, bh3);
            MMA(acc[1][2], ah0, ah1, ah2, ah3, bl2, bl3);
            wh += 128u; wl += 128u;             // advance 64 k (bf16 bytes)
        }
    };

    for (int p = 0; p <= 513; p++) {
        const bool act = (layer == 0) ? (p < 512) : (p >= 2);
        if (act) {
            const int t = (layer == 0) ? p : p - 2;
            const float* src_inp = (layer == 0) ? x + (size_t)t * 65536
                                                : g_h1[(p - 2) % 3];
            const float* src_rec = (layer == 0) ? g_h1[(p + 2) % 3]
                                                : g_h2[(p + 1) & 1];
            float* hout = (layer == 0) ? g_h1[p % 3] : g_h2[p & 1];

#pragma unroll
            for (int n = 0; n < 2; n++)
#pragma unroll
                for (int q = 0; q < 3; q++)
#pragma unroll
                    for (int e = 0; e < 4; e++) acc[n][q][e] = 0.0f;

            ghalf(src_inp, 0u);                       // pre-flip work

            while (ld_vol(&g_gen) < (unsigned)p) {}   // per-warp spin
            __syncwarp();

            ghalf(src_rec, 1024u);                    // post-flip work

            // ---- stash partials: red[kg][64 m][16 j] ----
#pragma unroll
            for (int n = 0; n < 2; n++) {
                float s0 = acc[n][0][0] + acc[n][1][0] + acc[n][2][0];
                float s1 = acc[n][0][1] + acc[n][1][1] + acc[n][2][1];
                float s2 = acc[n][0][2] + acc[n][1][2] + acc[n][2][2];
                float s3 = acc[n][0][3] + acc[n][1][3] + acc[n][2][3];
                int jn = n * 8 + lr * 2;
                *(float2*)&red[kg * 1024 + r0 * 16 + jn] = make_float2(s0, s1);
                *(float2*)&red[kg * 1024 + r1 * 16 + jn] = make_float2(s2, s3);
            }
            __syncthreads();
            {
                const int m = tid >> 3, jc = (tid & 7) * 2;
                float2 s2v = make_float2(0.f, 0.f);
#pragma unroll
                for (int g = 0; g < 4; g++) {
                    float2 v = *(const float2*)&red[g * 1024 + m * 16 + jc];
                    s2v.x += v.x; s2v.y += v.y;
                }
                float2 b2 = *(const float2*)&bias[jc];
                float2 h2;
                h2.x = fast_tanh(s2v.x + b2.x);
                h2.y = fast_tanh(s2v.y + b2.y);
                *(float2*)&hout[m * 1024 + col0 + jc] = h2;
                if (layer == 1) {
                    float2 o2 = make_float2(10.f * h2.x, 10.f * h2.y);
                    *(float2*)&out[(size_t)t * 65536 + m * 1024 + col0 + jc] = o2;
                }
                if (wr_hn && t == 511)
                    *(float2*)&out[HNOFF + (size_t)layer * 65536
                                   + m * 1024 + col0 + jc] = h2;
            }
        } else {
            while (ld_vol(&g_gen) < (unsigned)p) {}
        }
        __syncthreads();
        if (tid == 0) {
            __threadfence();
            if (atomicAdd(&g_cnt, 1u) == NCTA - 1u) {
                st_vol(&g_cnt, 0u);
                __threadfence();
                st_vol(&g_gen, (unsigned)p + 1u);
            }
        }
    }
}

extern "C" void kernel_launch(void* const* d_in, const int* in_sizes, int n_in,
                              void* d_out, int out_size) {
    const float* x  = (const float*)d_in[0];
    const float* h0 = (const float*)d_in[1];
    const float* Wx = (const float*)d_in[2];
    const float* bx = (const float*)d_in[3];
    const float* Wh = (const float*)d_in[4];
    const float* bh = (const float*)d_in[5];
    (void)in_sizes; (void)n_in;

    cudaFuncSetAttribute(rnn_main, cudaFuncAttributeMaxDynamicSharedMemorySize,
                         SMEM_BYTES);
    rnn_init<<<64, 256>>>(h0);
    rnn_main<<<NCTA, NTHR, SMEM_BYTES>>>(x, Wx, bx, Wh, bh,
                                         (float*)d_out, out_size);
}

// round 16
// speedup vs baseline: 2.6643x; 1.9163x over previous
#include <cuda_runtime.h>

#define NCTA 128
#define NTHR 512
#define KS   2056u                   // W bf16 row stride (elements)
#define WHI  0u
#define WLO  65792u                  // 16*2056*2
#define REDB 131584u                 // 4 kg * 64 m * 16 j * f32
#define BIASB 147968u
#define SMEM_BYTES 148032
#define HNOFF (512 * 64 * 1024)
#define FRAGN 32768                  // u32 per [64m x 1024k] fragment image

// fragment-layout A sources (bf16x2 packed in u32)
__device__ unsigned xfh[512 * FRAGN];   // 64 MB
__device__ unsigned xfl[512 * FRAGN];   // 64 MB
__device__ unsigned g1fh[3 * FRAGN], g1fl[3 * FRAGN];
__device__ unsigned g2fh[2 * FRAGN], g2fl[2 * FRAGN];
__device__ unsigned g_cnt, g_gen;

static __device__ __forceinline__ unsigned su32(const void* p) {
    return (unsigned)__cvta_generic_to_shared(p);
}
static __device__ __forceinline__ unsigned ld_vol(const unsigned* p) {
    unsigned v;
    asm volatile("ld.volatile.global.u32 %0,[%1];" : "=r"(v) : "l"(p));
    return v;
}
static __device__ __forceinline__ void st_vol(unsigned* p, unsigned v) {
    asm volatile("st.volatile.global.u32 [%0],%1;" :: "l"(p), "r"(v));
}
static __device__ __forceinline__ uint4 ldcg4(const uint4* p) {
    uint4 v;
    asm volatile("ld.global.cg.v4.u32 {%0,%1,%2,%3},[%4];"
                 : "=r"(v.x), "=r"(v.y), "=r"(v.z), "=r"(v.w) : "l"(p));
    return v;
}
// split fp32 pair -> bf16x2 hi (truncate) + lo (residual, rn)
static __device__ __forceinline__ void split2(float2 v, unsigned& h, unsigned& l) {
    unsigned u0 = __float_as_uint(v.x), u1 = __float_as_uint(v.y);
    asm("prmt.b32 %0,%1,%2,0x7632;" : "=r"(h) : "r"(u0), "r"(u1));
    float l0 = v.x - __uint_as_float(u0 & 0xFFFF0000u);
    float l1 = v.y - __uint_as_float(u1 & 0xFFFF0000u);
    asm("cvt.rn.bf16x2.f32 %0,%1,%2;" : "=r"(l) : "f"(l1), "f"(l0));
}
#define LDSMX4(r0, r1, r2, r3, a) \
    asm volatile("ldmatrix.sync.aligned.m8n8.x4.shared.b16 {%0,%1,%2,%3},[%4];" \
                 : "=r"(r0), "=r"(r1), "=r"(r2), "=r"(r3) : "r"(a))
#define MMA(c, A0, A1, A2, A3, B0, B1) \
    asm("mma.sync.aligned.m16n8k16.row.col.f32.bf16.bf16.f32 " \
        "{%0,%1,%2,%3},{%4,%5,%6,%7},{%8,%9},{%0,%1,%2,%3};" \
        : "+f"(c[0]), "+f"(c[1]), "+f"(c[2]), "+f"(c[3]) \
        : "r"(A0), "r"(A1), "r"(A2), "r"(A3), "r"(B0), "r"(B1))

static __device__ __forceinline__ float fast_tanh(float v) {
    float e = __expf(2.0f * v);
    return 1.0f - __fdividef(2.0f, e + 1.0f);
}

// convert 4 float2 quadrants of one (mt,kb,lane) cell into hi/lo uint4
static __device__ __forceinline__ void conv_cell(const float* s, int m, int k,
                                                 uint4& oh, uint4& ol) {
    float2 v0 = *(const float2*)(s + (size_t)m * 1024 + k);
    float2 v1 = *(const float2*)(s + (size_t)(m + 8) * 1024 + k);
    float2 v2 = *(const float2*)(s + (size_t)m * 1024 + k + 8);
    float2 v3 = *(const float2*)(s + (size_t)(m + 8) * 1024 + k + 8);
    split2(v0, oh.x, ol.x); split2(v1, oh.y, ol.y);
    split2(v2, oh.z, ol.z); split2(v3, oh.w, ol.w);
}

// ---- x -> fragment layout (once per graph replay) ----
__global__ void __launch_bounds__(512) xconv(const float* __restrict__ x) {
    int idx = blockIdx.x * 512 + threadIdx.x;       // 512*8192 threads
    int t = idx >> 13, r = idx & 8191;
    int mt = r >> 11, kb = (r >> 5) & 63, lane = r & 31;
    int m = mt * 16 + (lane >> 2), k = kb * 16 + (lane & 3) * 2;
    uint4 oh, ol;
    conv_cell(x + (size_t)t * 65536, m, k, oh, ol);
    ((uint4*)xfh)[idx] = oh;
    ((uint4*)xfl)[idx] = ol;
}

// ---- h0 -> fragment layout + barrier reset ----
__global__ void __launch_bounds__(256) rnn_init(const float* __restrict__ h0) {
    int idx = blockIdx.x * 256 + threadIdx.x;       // 16384 threads
    int layer = idx >> 13, r = idx & 8191;
    int mt = r >> 11, kb = (r >> 5) & 63, lane = r & 31;
    int m = mt * 16 + (lane >> 2), k = kb * 16 + (lane & 3) * 2;
    uint4 oh, ol;
    conv_cell(h0 + (size_t)layer * 65536, m, k, oh, ol);
    if (layer == 0) {                // h1[t=-1] in slot 2
        ((uint4*)g1fh)[2 * 8192 + r] = oh;
        ((uint4*)g1fl)[2 * 8192 + r] = ol;
    } else {                          // h2[t=-1] in slot 1
        ((uint4*)g2fh)[1 * 8192 + r] = oh;
        ((uint4*)g2fl)[1 * 8192 + r] = ol;
    }
    if (idx == 0) { g_cnt = 0u; g_gen = 0u; }
}

__global__ void __launch_bounds__(NTHR, 1) rnn_main(
    const float* __restrict__ Wx, const float* __restrict__ bx,
    const float* __restrict__ Wh, const float* __restrict__ bh,
    float* __restrict__ out, int out_size)
{
    extern __shared__ char smem[];
    float* red = (float*)(smem + REDB);
    float* bias = (float*)(smem + BIASB);
    const int tid = threadIdx.x, cta = blockIdx.x;
    const int layer = cta >> 6, col0 = (cta & 63) * 16;

    // ---- convert fused W slice [16 j][2048 k] fp32 -> bf16 hi/lo in SMEM ----
    {
        const float* wxl = Wx + (size_t)layer * 1048576 + (size_t)col0 * 1024;
        const float* whl = Wh + (size_t)layer * 1048576 + (size_t)col0 * 1024;
        for (int r = 0; r < 32; r++) {
            int idx = r * NTHR + tid;
            int j = idx >> 10, k = (idx & 1023) * 2;
            const float* s = (k < 1024) ? wxl + j * 1024 + k
                                        : whl + j * 1024 + (k - 1024);
            float2 v = *(const float2*)s;
            unsigned hp, lp;
            split2(v, hp, lp);
            *(unsigned*)(smem + WHI + ((unsigned)j * KS + k) * 2u) = hp;
            *(unsigned*)(smem + WLO + ((unsigned)j * KS + k) * 2u) = lp;
        }
        if (tid < 16)
            bias[tid] = bx[layer * 1024 + col0 + tid]
                      + bh[layer * 1024 + col0 + tid];
        __syncthreads();
    }

    // 16 warps = 4 m-tiles x 4 k-groups
    const int wid = tid >> 5, lane = tid & 31;
    const int mt = wid & 3, kg = wid >> 2;
    const int lq = lane >> 2, lr = lane & 3;
    const int r0 = mt * 16 + lq, r1 = r0 + 8;
    const bool wr_hn = out_size >= HNOFF + 131072;
    const unsigned sbase = su32(smem);
    const int sel = lane >> 3;
    const int nrow = (lane & 7) + ((sel >> 1) << 3);
    const unsigned wl0 = sbase
        + ((unsigned)nrow * KS + (unsigned)(kg * 16) + (unsigned)((sel & 1) * 8)) * 2u;
    // this warp's fragment index base within a [4mt][64kb][32lane] image
    const unsigned fbase = (unsigned)((mt * 64 + kg) * 32 + lane);

    float acc[2][2][4];

    // one half-GEMM over fragment images fh/fl (8192 uint4); W k-base = hb
    auto ghalf = [&](const unsigned* fh, const unsigned* fl, unsigned hb) {
        const uint4* ph = (const uint4*)fh + fbase;
        const uint4* pl = (const uint4*)fl + fbase;
        uint4 bh[2], bl[2];
        bh[0] = ldcg4(ph); bl[0] = ldcg4(pl);
        ph += 128; pl += 128;                    // 4 kb * 32 lanes
        bh[1] = ldcg4(ph); bl[1] = ldcg4(pl);
        unsigned wh = wl0 + hb * 2u;
        unsigned wl = wh + WLO;
#pragma unroll 4
        for (int i = 0; i < 16; i++) {
            uint4 ah = bh[i & 1], al = bl[i & 1];
            if (i < 14) {                        // prefetch iter i+2
                ph += 128; pl += 128;
                bh[i & 1] = ldcg4(ph); bl[i & 1] = ldcg4(pl);
            }
            unsigned b0, b1, b2, b3, c0, c1, c2, c3;
            LDSMX4(b0, b1, b2, b3, wh);
            LDSMX4(c0, c1, c2, c3, wl);
            MMA(acc[0][0], ah.x, ah.y, ah.z, ah.w, b0, b1);
            MMA(acc[0][1], al.x, al.y, al.z, al.w, b0, b1);
            MMA(acc[0][1], ah.x, ah.y, ah.z, ah.w, c0, c1);
            MMA(acc[1][0], ah.x, ah.y, ah.z, ah.w, b2, b3);
            MMA(acc[1][1], al.x, al.y, al.z, al.w, b2, b3);
            MMA(acc[1][1], ah.x, ah.y, ah.z, ah.w, c2, c3);
            wh += 128u; wl += 128u;              // advance 64 k
        }
    };

    for (int p = 0; p <= 513; p++) {
        const bool act = (layer == 0) ? (p < 512) : (p >= 2);
        if (act) {
            const int t = (layer == 0) ? p : p - 2;
            const unsigned* ih = (layer == 0) ? xfh + (size_t)t * FRAGN
                                              : g1fh + ((p - 2) % 3) * FRAGN;
            const unsigned* il = (layer == 0) ? xfl + (size_t)t * FRAGN
                                              : g1fl + ((p - 2) % 3) * FRAGN;
            const unsigned* rh = (layer == 0) ? g1fh + ((p + 2) % 3) * FRAGN
                                              : g2fh + ((p + 1) & 1) * FRAGN;
            const unsigned* rl = (layer == 0) ? g1fl + ((p + 2) % 3) * FRAGN
                                              : g2fl + ((p + 1) & 1) * FRAGN;
            unsigned* oh = (layer == 0) ? g1fh + (p % 3) * FRAGN
                                        : g2fh + (p & 1) * FRAGN;
            unsigned* ol = (layer == 0) ? g1fl + (p % 3) * FRAGN
                                        : g2fl + (p & 1) * FRAGN;

#pragma unroll
            for (int n = 0; n < 2; n++)
#pragma unroll
                for (int q = 0; q < 2; q++)
#pragma unroll
                    for (int e = 0; e < 4; e++) acc[n][q][e] = 0.0f;

            ghalf(ih, il, 0u);                        // pre-flip work

            while (ld_vol(&g_gen) < (unsigned)p) {}   // per-warp spin
            __syncwarp();

            ghalf(rh, rl, 1024u);                     // post-flip work

            // ---- stash partials: red[kg][64 m][16 j] ----
#pragma unroll
            for (int n = 0; n < 2; n++) {
                float s0 = acc[n][0][0] + acc[n][1][0];
                float s1 = acc[n][0][1] + acc[n][1][1];
                float s2 = acc[n][0][2] + acc[n][1][2];
                float s3 = acc[n][0][3] + acc[n][1][3];
                int jn = n * 8 + lr * 2;
                *(float2*)&red[kg * 1024 + r0 * 16 + jn] = make_float2(s0, s1);
                *(float2*)&red[kg * 1024 + r1 * 16 + jn] = make_float2(s2, s3);
            }
            __syncthreads();
            {
                const int m = tid >> 3, jc = (tid & 7) * 2;
                float2 s2v = make_float2(0.f, 0.f);
#pragma unroll
                for (int g = 0; g < 4; g++) {
                    float2 v = *(const float2*)&red[g * 1024 + m * 16 + jc];
                    s2v.x += v.x; s2v.y += v.y;
                }
                float2 b2 = *(const float2*)&bias[jc];
                float2 h2;
                h2.x = fast_tanh(s2v.x + b2.x);
                h2.y = fast_tanh(s2v.y + b2.y);
                // write h in fragment layout (bf16 hi/lo)
                unsigned hh, hl;
                split2(h2, hh, hl);
                const int k = col0 + jc;
                unsigned off = ((unsigned)((m >> 4) * 64 + (k >> 4)) * 32u
                                + (unsigned)(((m & 7) << 2) | ((k & 7) >> 1))) * 4u
                               + (unsigned)(((m >> 3) & 1) | (((k >> 3) & 1) << 1));
                oh[off] = hh; ol[off] = hl;
                if (layer == 1) {
                    float2 o2 = make_float2(10.f * h2.x, 10.f * h2.y);
                    *(float2*)&out[(size_t)t * 65536 + m * 1024 + k] = o2;
                }
                if (wr_hn && t == 511)
                    *(float2*)&out[HNOFF + (size_t)layer * 65536
                                   + m * 1024 + k] = h2;
            }
        } else {
            while (ld_vol(&g_gen) < (unsigned)p) {}
        }
        __syncthreads();
        if (tid == 0) {
            __threadfence();
            if (atomicAdd(&g_cnt, 1u) == NCTA - 1u) {
                st_vol(&g_cnt, 0u);
                __threadfence();
                st_vol(&g_gen, (unsigned)p + 1u);
            }
        }
    }
}

extern "C" void kernel_launch(void* const* d_in, const int* in_sizes, int n_in,
                              void* d_out, int out_size) {
    const float* x  = (const float*)d_in[0];
    const float* h0 = (const float*)d_in[1];
    const float* Wx = (const float*)d_in[2];
    const float* bx = (const float*)d_in[3];
    const float* Wh = (const float*)d_in[4];
    const float* bh = (const float*)d_in[5];
    (void)in_sizes; (void)n_in;

    cudaFuncSetAttribute(rnn_main, cudaFuncAttributeMaxDynamicSharedMemorySize,
                         SMEM_BYTES);
    xconv<<<8192, 512>>>(x);
    rnn_init<<<64, 256>>>(h0);
    rnn_main<<<NCTA, NTHR, SMEM_BYTES>>>(Wx, bx, Wh, bh,
                                         (float*)d_out, out_size);
}